// round 12
// baseline (speedup 1.0000x reference)
#include <cuda_runtime.h>
#include <math.h>
#include <string.h>

#define MAXE 48

// ---------------- device-global scratch (weight/wpath-dependent only) ----------------
__device__ float g_w1[768];          // pre-contracted W3@Wt1 : [p][l][128]
__device__ float g_w2[768];          // pre-contracted W3@Wt2
__device__ float g_c1, g_c2;         // bias scalars for (p=0, lm=0)
__device__ float g_lval[9 * MAXE];   // CG * wpath, per-c sparse lists

// ---------------- host-computed constants passed by value (constant bank) ----------------
struct PrepConst {
    float         cgv[9 * MAXE];     // CG value per sparse entry (0 in unused slots)
    unsigned char wpidx[9 * MAXE];   // wpath flat index per sparse entry
};
struct MainConst {
    float         cgos[81];          // CG[1+i][1+j][c] laid out [k=i*3+j][c]
    int           lcnt[9];           // sparse-list counts per output c
    unsigned char lab[9 * MAXE];     // packed (a<<4)|b per sparse entry
};

// ================= HOST: Clebsch-Gordan construction (double precision) =================
static inline int h_lof(int i) { return i >= 4 ? 2 : (i >= 1 ? 1 : 0); }

static double h_dfact(int n) {
    static const double F[8] = {1., 1., 2., 6., 24., 120., 720., 5040.};
    return F[n];
}

static double h_cg_complex(int j1, int m1, int j2, int m2, int j3, int m3) {
    if (m3 != m1 + m2) return 0.0;
    int lo = j1 - j2; if (lo < 0) lo = -lo;
    if (j3 < lo || j3 > j1 + j2) return 0.0;
    double pref = sqrt((2.0 * j3 + 1.0) * h_dfact(j1 + j2 - j3) * h_dfact(j1 - j2 + j3) *
                       h_dfact(-j1 + j2 + j3) / h_dfact(j1 + j2 + j3 + 1));
    pref *= sqrt(h_dfact(j1 + m1) * h_dfact(j1 - m1) * h_dfact(j2 + m2) * h_dfact(j2 - m2) *
                 h_dfact(j3 + m3) * h_dfact(j3 - m3));
    double s = 0.0;
    for (int k = 0; k <= j1 + j2 - j3; k++) {
        int t1 = j1 + j2 - j3 - k, t2 = j1 - m1 - k, t3 = j2 + m2 - k;
        int t4 = j3 - j2 + m1 + k, t5 = j3 - j1 - m2 + k;
        if (t1 < 0 || t2 < 0 || t3 < 0 || t4 < 0 || t5 < 0) continue;
        double d = h_dfact(k) * h_dfact(t1) * h_dfact(t2) * h_dfact(t3) * h_dfact(t4) * h_dfact(t5);
        s += ((k & 1) ? -1.0 : 1.0) / d;
    }
    return pref * s;
}

// complex->real basis matrix entry; rows ordered m=-l..l. r,c in 0..2l
static void h_umat_entry(int l, int r, int c, double* re, double* im) {
    *re = 0.0; *im = 0.0;
    int mr = r - l, mc = c - l;
    const double inv = 0.70710678118654752440;
    if (mr == 0) { if (mc == 0) *re = 1.0; return; }
    if (mr > 0) {
        int m = mr; double sgn = (m & 1) ? -1.0 : 1.0;
        if (mc == -m) *re = inv;
        else if (mc == m) *re = sgn * inv;
    } else {
        int m = -mr; double sgn = (m & 1) ? -1.0 : 1.0;
        if (mc == -m) *im = inv;
        else if (mc == m) *im = -sgn * inv;
    }
}

static void h_build_cg(float* cg /*729*/) {
    for (int t = 0; t < 729; t++) {
        int a = t / 81, b = (t / 9) % 9, c = t % 9;
        int l1 = h_lof(a), l2 = h_lof(b), l3 = h_lof(c);
        double re = 0.0, im = 0.0;
        int lo = l1 - l2; if (lo < 0) lo = -lo;
        if (l3 >= lo && l3 <= l1 + l2) {
            int aa = a - l1 * l1, bb = b - l2 * l2, cc = c - l3 * l3;
            for (int m = 0; m < 2 * l1 + 1; m++) {
                double u1r, u1i; h_umat_entry(l1, aa, m, &u1r, &u1i); u1i = -u1i;  // conj
                if (u1r == 0.0 && u1i == 0.0) continue;
                for (int nn = 0; nn < 2 * l2 + 1; nn++) {
                    double u2r, u2i; h_umat_entry(l2, bb, nn, &u2r, &u2i); u2i = -u2i;  // conj
                    if (u2r == 0.0 && u2i == 0.0) continue;
                    double pr = u1r * u2r - u1i * u2i;
                    double pi = u1r * u2i + u1i * u2r;
                    for (int o = 0; o < 2 * l3 + 1; o++) {
                        double u3r, u3i; h_umat_entry(l3, cc, o, &u3r, &u3i);
                        if (u3r == 0.0 && u3i == 0.0) continue;
                        double C = h_cg_complex(l1, m - l1, l2, nn - l2, l3, o - l3);
                        if (C == 0.0) continue;
                        re += (pr * u3r - pi * u3i) * C;
                        im += (pr * u3i + pi * u3r) * C;
                    }
                }
            }
        }
        double val = ((l1 + l2 + l3) & 1) ? im : re;
        cg[t] = (float)val;
    }
}

// ================= DEVICE: prelude (weights + wpath-scaled lists), single launch =========
__global__ void k_prep(const float* __restrict__ W3, const float* __restrict__ b3,
                       const float* __restrict__ Wt1, const float* __restrict__ bt1,
                       const float* __restrict__ Wt2, const float* __restrict__ bt2,
                       const float* __restrict__ wpath, PrepConst pc) {
    int t = blockIdx.x * blockDim.x + threadIdx.x;
    if (t < 768) {
        int pl = t >> 7, i = t & 127;
        const float* w3 = W3 + ((size_t)pl * 128 + i) * 128;
        const float* v1 = Wt1 + pl * 128;
        const float* v2 = Wt2 + pl * 128;
        float a1 = 0.f, a2 = 0.f;
        #pragma unroll 8
        for (int o = 0; o < 128; o++) {
            float w = w3[o];
            a1 = fmaf(w, v1[o], a1);
            a2 = fmaf(w, v2[o], a2);
        }
        g_w1[t] = a1; g_w2[t] = a2;
    } else if (t == 768) {
        float a1 = bt1[0], a2 = bt2[0];
        for (int o = 0; o < 128; o++) {
            float bo = b3[o];
            a1 = fmaf(bo, Wt1[o], a1);
            a2 = fmaf(bo, Wt2[o], a2);
        }
        g_c1 = a1; g_c2 = a2;
    } else if (t >= 800 && t < 800 + 9 * MAXE) {
        int i = t - 800;
        g_lval[i] = pc.cgv[i] * wpath[pc.wpidx[i]];
    }
}

// ================= DEVICE: main streaming kernel =================
__device__ __forceinline__ float dot4(float4 v, float4 w) {
    return fmaf(v.x, w.x, fmaf(v.y, w.y, fmaf(v.z, w.z, v.w * w.w)));
}

__global__ void __launch_bounds__(256, 2)
k_main(const float* __restrict__ sf, float* __restrict__ out, int N, MainConst mc) {
    __shared__ float w1s[768];
    __shared__ float w2s[768];
    __shared__ float cgos[81];
    __shared__ int   lcnt_s[9];
    __shared__ unsigned char lab_s[9 * MAXE];
    __shared__ float lval_s[9 * MAXE];
    __shared__ float xbuf[32][36];       // per-subgroup x1[18], x2[18]
    __shared__ float tpbuf[32][9];

    int tid = threadIdx.x;
    for (int i = tid; i < 768; i += 256) { w1s[i] = g_w1[i]; w2s[i] = g_w2[i]; }
    for (int i = tid; i < 9 * MAXE; i += 256) { lval_s[i] = g_lval[i]; lab_s[i] = mc.lab[i]; }
    if (tid < 81) cgos[tid] = mc.cgos[tid];
    if (tid < 9)  lcnt_s[tid] = mc.lcnt[tid];
    float c1 = g_c1, c2 = g_c2;
    __syncthreads();

    int warp = tid >> 5, lane = tid & 31;
    int g = lane >> 3, s = lane & 7;            // 4 subgroups of 8 lanes; one n per subgroup
    int sub = (warp << 2) | g;
    int n = (blockIdx.x * 8 + warp) * 4 + g;
    bool active = n < N;
    size_t nn = active ? (size_t)n : 0;

    const float4* sfp = reinterpret_cast<const float4*>(sf) + nn * 576;  // 2*9*32 float4 per n

    // ---- phase 1: 36 partial dots, all 72 LDG.128 dependency-free (max MLP) ----
    float s1[18], s2[18];
    {
        int r = 0;
        #pragma unroll
        for (int p = 0; p < 2; p++) {
            #pragma unroll
            for (int l = 0; l < 3; l++) {
                const float4* w1p = reinterpret_cast<const float4*>(w1s) + (p * 3 + l) * 32;
                const float4* w2p = reinterpret_cast<const float4*>(w2s) + (p * 3 + l) * 32;
                float4 a0 = w1p[s], a1 = w1p[s + 8], a2 = w1p[s + 16], a3 = w1p[s + 24];
                float4 b0 = w2p[s], b1 = w2p[s + 8], b2 = w2p[s + 16], b3v = w2p[s + 24];
                const int nlm = 2 * l + 1;
                #pragma unroll
                for (int j = 0; j < nlm; j++) {
                    const float4* rp = sfp + (p * 9 + l * l + j) * 32;
                    float4 v0 = rp[s], v1 = rp[s + 8], v2 = rp[s + 16], v3 = rp[s + 24];
                    s1[r] = dot4(v0, a0) + dot4(v1, a1) + dot4(v2, a2) + dot4(v3, a3);
                    s2[r] = dot4(v0, b0) + dot4(v1, b1) + dot4(v2, b2) + dot4(v3, b3v);
                    r++;
                }
            }
        }
    }

    // ---- phase 2: width-8 butterfly reduction (stays inside subgroup) ----
    #pragma unroll
    for (int r = 0; r < 18; r++) {
        s1[r] += __shfl_xor_sync(0xffffffffu, s1[r], 1);
        s1[r] += __shfl_xor_sync(0xffffffffu, s1[r], 2);
        s1[r] += __shfl_xor_sync(0xffffffffu, s1[r], 4);
        s2[r] += __shfl_xor_sync(0xffffffffu, s2[r], 1);
        s2[r] += __shfl_xor_sync(0xffffffffu, s2[r], 2);
        s2[r] += __shfl_xor_sync(0xffffffffu, s2[r], 4);
    }
    s1[0] += c1;   // bias on even-parity scalar channel
    s2[0] += c2;

    if (s == 0) {
        #pragma unroll
        for (int r = 0; r < 18; r++) { xbuf[sub][r] = s1[r]; xbuf[sub][18 + r] = s2[r]; }
    }
    __syncwarp();

    // ---- phase 3: sparse tensor product tp[c] (lanes split the 9 c's) ----
    for (int c = s; c < 9; c += 8) {
        float tp = 0.f;
        int cnt = lcnt_s[c];
        const unsigned char* pab = lab_s + c * MAXE;
        const float*         pv  = lval_s + c * MAXE;
        for (int e = 0; e < cnt; e++) {
            int ab = pab[e];
            float val = pv[e];
            int a = ab >> 4, b = ab & 15;
            float t0 = xbuf[sub][a] * xbuf[sub][18 + b];
            float t1 = fmaf(xbuf[sub][9 + a], xbuf[sub][27 + b], t0);
            tp = fmaf(val, t1, tp);
        }
        tpbuf[sub][c] = tp;
    }
    __syncwarp();

    // ---- phase 4: out[i,j] = sum_c tp[c] * CG[1+i,1+j,c] ----
    for (int k = s; k < 9; k += 8) {
        float o = 0.f;
        #pragma unroll
        for (int c = 0; c < 9; c++) o = fmaf(tpbuf[sub][c], cgos[k * 9 + c], o);
        if (active) out[(size_t)n * 9 + k] = o;
    }
}

// ================= launch =================
extern "C" void kernel_launch(void* const* d_in, const int* in_sizes, int n_in,
                              void* d_out, int out_size) {
    const float* sf    = (const float*)d_in[0];
    const float* W3    = (const float*)d_in[1];
    const float* b3    = (const float*)d_in[2];
    const float* Wt1   = (const float*)d_in[3];
    const float* bt1   = (const float*)d_in[4];
    const float* Wt2   = (const float*)d_in[5];
    const float* bt2   = (const float*)d_in[6];
    const float* wpath = (const float*)d_in[7];

    int N = in_sizes[0] / 2304;  // N * 2 * 9 * 128

    // ---- host-side constant construction (pure CPU, graph-safe) ----
    float cg[729];
    h_build_cg(cg);

    PrepConst pc;
    MainConst mcst;
    memset(&pc, 0, sizeof(pc));
    memset(&mcst, 0, sizeof(mcst));

    for (int t = 0; t < 81; t++) {
        int k = t / 9, c = t % 9;
        int ii = k / 3, jj = k % 3;
        mcst.cgos[t] = cg[(1 + ii) * 81 + (1 + jj) * 9 + c];
    }
    for (int c = 0; c < 9; c++) {
        int cnt = 0;
        for (int ab = 0; ab < 81; ab++) {
            int idx = ab * 9 + c;
            if (fabsf(cg[idx]) > 1e-6f && cnt < MAXE) {
                int a = ab / 9, b = ab % 9;
                mcst.lab[c * MAXE + cnt] = (unsigned char)((a << 4) | b);
                pc.cgv[c * MAXE + cnt]   = cg[idx];
                pc.wpidx[c * MAXE + cnt] = (unsigned char)((h_lof(a) * 3 + h_lof(b)) * 3 + h_lof(c));
                cnt++;
            }
        }
        mcst.lcnt[c] = cnt;
    }

    // ---- device work: one tiny prelude + one streaming kernel ----
    k_prep<<<5, 256>>>(W3, b3, Wt1, bt1, Wt2, bt2, wpath, pc);

    int blocks = (N + 31) / 32;                  // 32 n per block (8 warps x 4 subgroups)
    k_main<<<blocks, 256>>>(sf, (float*)d_out, N, mcst);
}

// round 13
// speedup vs baseline: 1.0301x; 1.0301x over previous
#include <cuda_runtime.h>
#include <math.h>
#include <string.h>

#define MAXE 48

// ---------------- device-global scratch (weight/wpath-dependent only) ----------------
__device__ float g_w1[768];          // pre-contracted W3@Wt1 : [p][l][128]
__device__ float g_w2[768];          // pre-contracted W3@Wt2
__device__ float g_c1, g_c2;         // bias scalars for (p=0, lm=0)
__device__ float g_lval[9 * MAXE];   // CG * wpath, per-c sparse lists

// ---------------- host-computed constants passed by value (constant bank) ----------------
struct PrepConst {
    float         cgv[9 * MAXE];     // CG value per sparse entry (0 in unused slots)
    unsigned char wpidx[9 * MAXE];   // wpath flat index per sparse entry
};
struct MainConst {
    float         cgos[81];          // CG[1+i][1+j][c] laid out [k=i*3+j][c]
    int           lcnt[9];           // sparse-list counts per output c
    unsigned char lab[9 * MAXE];     // packed (a<<4)|b per sparse entry
};

// ================= HOST: Clebsch-Gordan construction (double precision) =================
static inline int h_lof(int i) { return i >= 4 ? 2 : (i >= 1 ? 1 : 0); }

static double h_dfact(int n) {
    static const double F[8] = {1., 1., 2., 6., 24., 120., 720., 5040.};
    return F[n];
}

static double h_cg_complex(int j1, int m1, int j2, int m2, int j3, int m3) {
    if (m3 != m1 + m2) return 0.0;
    int lo = j1 - j2; if (lo < 0) lo = -lo;
    if (j3 < lo || j3 > j1 + j2) return 0.0;
    double pref = sqrt((2.0 * j3 + 1.0) * h_dfact(j1 + j2 - j3) * h_dfact(j1 - j2 + j3) *
                       h_dfact(-j1 + j2 + j3) / h_dfact(j1 + j2 + j3 + 1));
    pref *= sqrt(h_dfact(j1 + m1) * h_dfact(j1 - m1) * h_dfact(j2 + m2) * h_dfact(j2 - m2) *
                 h_dfact(j3 + m3) * h_dfact(j3 - m3));
    double s = 0.0;
    for (int k = 0; k <= j1 + j2 - j3; k++) {
        int t1 = j1 + j2 - j3 - k, t2 = j1 - m1 - k, t3 = j2 + m2 - k;
        int t4 = j3 - j2 + m1 + k, t5 = j3 - j1 - m2 + k;
        if (t1 < 0 || t2 < 0 || t3 < 0 || t4 < 0 || t5 < 0) continue;
        double d = h_dfact(k) * h_dfact(t1) * h_dfact(t2) * h_dfact(t3) * h_dfact(t4) * h_dfact(t5);
        s += ((k & 1) ? -1.0 : 1.0) / d;
    }
    return pref * s;
}

// complex->real basis matrix entry; rows ordered m=-l..l. r,c in 0..2l
static void h_umat_entry(int l, int r, int c, double* re, double* im) {
    *re = 0.0; *im = 0.0;
    int mr = r - l, mc = c - l;
    const double inv = 0.70710678118654752440;
    if (mr == 0) { if (mc == 0) *re = 1.0; return; }
    if (mr > 0) {
        int m = mr; double sgn = (m & 1) ? -1.0 : 1.0;
        if (mc == -m) *re = inv;
        else if (mc == m) *re = sgn * inv;
    } else {
        int m = -mr; double sgn = (m & 1) ? -1.0 : 1.0;
        if (mc == -m) *im = inv;
        else if (mc == m) *im = -sgn * inv;
    }
}

static void h_build_cg(float* cg /*729*/) {
    for (int t = 0; t < 729; t++) {
        int a = t / 81, b = (t / 9) % 9, c = t % 9;
        int l1 = h_lof(a), l2 = h_lof(b), l3 = h_lof(c);
        double re = 0.0, im = 0.0;
        int lo = l1 - l2; if (lo < 0) lo = -lo;
        if (l3 >= lo && l3 <= l1 + l2) {
            int aa = a - l1 * l1, bb = b - l2 * l2, cc = c - l3 * l3;
            for (int m = 0; m < 2 * l1 + 1; m++) {
                double u1r, u1i; h_umat_entry(l1, aa, m, &u1r, &u1i); u1i = -u1i;  // conj
                if (u1r == 0.0 && u1i == 0.0) continue;
                for (int nn = 0; nn < 2 * l2 + 1; nn++) {
                    double u2r, u2i; h_umat_entry(l2, bb, nn, &u2r, &u2i); u2i = -u2i;  // conj
                    if (u2r == 0.0 && u2i == 0.0) continue;
                    double pr = u1r * u2r - u1i * u2i;
                    double pi = u1r * u2i + u1i * u2r;
                    for (int o = 0; o < 2 * l3 + 1; o++) {
                        double u3r, u3i; h_umat_entry(l3, cc, o, &u3r, &u3i);
                        if (u3r == 0.0 && u3i == 0.0) continue;
                        double C = h_cg_complex(l1, m - l1, l2, nn - l2, l3, o - l3);
                        if (C == 0.0) continue;
                        re += (pr * u3r - pi * u3i) * C;
                        im += (pr * u3i + pi * u3r) * C;
                    }
                }
            }
        }
        double val = ((l1 + l2 + l3) & 1) ? im : re;
        cg[t] = (float)val;
    }
}

// ================= DEVICE: prelude — warp-per-output dot products =================
__device__ __forceinline__ float dot4(float4 v, float4 w) {
    return fmaf(v.x, w.x, fmaf(v.y, w.y, fmaf(v.z, w.z, v.w * w.w)));
}

// grid = 97 blocks of 256. Blocks 0..95: 8 warps each, warp computes one of 768
// pre-contracted weights (128-dot spread over 32 lanes). Block 96: warp 0 does the
// bias dot; warps 1..7 scale the sparse CG lists by wpath.
__global__ void k_prep(const float* __restrict__ W3, const float* __restrict__ b3,
                       const float* __restrict__ Wt1, const float* __restrict__ bt1,
                       const float* __restrict__ Wt2, const float* __restrict__ bt2,
                       const float* __restrict__ wpath, PrepConst pc) {
    int tid = threadIdx.x;
    int warp = tid >> 5, lane = tid & 31;

    if (blockIdx.x < 96) {
        int t = blockIdx.x * 8 + warp;            // 0..767 output index
        int pl = t >> 7;
        const float4* w3r = reinterpret_cast<const float4*>(W3) + (size_t)t * 32;
        const float4* v1r = reinterpret_cast<const float4*>(Wt1) + pl * 32;
        const float4* v2r = reinterpret_cast<const float4*>(Wt2) + pl * 32;
        float4 w = w3r[lane];
        float a1 = dot4(w, v1r[lane]);
        float a2 = dot4(w, v2r[lane]);
        #pragma unroll
        for (int d = 16; d > 0; d >>= 1) {
            a1 += __shfl_xor_sync(0xffffffffu, a1, d);
            a2 += __shfl_xor_sync(0xffffffffu, a2, d);
        }
        if (lane == 0) { g_w1[t] = a1; g_w2[t] = a2; }
    } else {
        if (warp == 0) {
            const float4* br  = reinterpret_cast<const float4*>(b3);
            const float4* v1r = reinterpret_cast<const float4*>(Wt1);
            const float4* v2r = reinterpret_cast<const float4*>(Wt2);
            float4 b = br[lane];
            float a1 = dot4(b, v1r[lane]);
            float a2 = dot4(b, v2r[lane]);
            #pragma unroll
            for (int d = 16; d > 0; d >>= 1) {
                a1 += __shfl_xor_sync(0xffffffffu, a1, d);
                a2 += __shfl_xor_sync(0xffffffffu, a2, d);
            }
            if (lane == 0) { g_c1 = a1 + bt1[0]; g_c2 = a2 + bt2[0]; }
        } else {
            for (int i = tid - 32; i < 9 * MAXE; i += 224)
                g_lval[i] = pc.cgv[i] * wpath[pc.wpidx[i]];
        }
    }
}

// ================= DEVICE: main streaming kernel =================
// One n per warp. Lanes 0-15 handle parity 0, lanes 16-31 parity 1.
// Each lane owns float4 stripes {s, s+16} of each 512B row -> 18 accumulators/lane,
// all 18 LDG.128 per warp dependency-free, 4 full 128B lines per instruction.
__global__ void __launch_bounds__(256, 3)
k_main(const float* __restrict__ sf, float* __restrict__ out, int N, MainConst mc) {
    __shared__ float w1s[768];
    __shared__ float w2s[768];
    __shared__ float cgos[81];
    __shared__ int   lcnt_s[9];
    __shared__ unsigned char lab_s[9 * MAXE];
    __shared__ float lval_s[9 * MAXE];
    __shared__ float xbuf[8][36];        // per-warp: x1[p][9] then x2[p][9]
    __shared__ float tpbuf[8][9];

    int tid = threadIdx.x;
    for (int i = tid; i < 768; i += 256) { w1s[i] = g_w1[i]; w2s[i] = g_w2[i]; }
    for (int i = tid; i < 9 * MAXE; i += 256) { lval_s[i] = g_lval[i]; lab_s[i] = mc.lab[i]; }
    if (tid < 81) cgos[tid] = mc.cgos[tid];
    if (tid < 9)  lcnt_s[tid] = mc.lcnt[tid];
    float c1 = g_c1, c2 = g_c2;
    __syncthreads();

    int warp = tid >> 5, lane = tid & 31;
    int h = lane >> 4;                   // parity handled by this half-warp
    int s = lane & 15;                   // stripe index 0..15

    int n = blockIdx.x * 8 + warp;
    bool active = n < N;
    size_t nn = active ? (size_t)n : 0;

    const float4* sfp = reinterpret_cast<const float4*>(sf) + nn * 576 + (size_t)h * 288;

    // ---- phase 1: 18 partial dots per lane (9 rows x {x1,x2}), loads front-batchable ----
    float s1[9], s2[9];
    {
        int r = 0;
        #pragma unroll
        for (int l = 0; l < 3; l++) {
            const float4* w1p = reinterpret_cast<const float4*>(w1s) + (h * 3 + l) * 32;
            const float4* w2p = reinterpret_cast<const float4*>(w2s) + (h * 3 + l) * 32;
            float4 a0 = w1p[s], a1 = w1p[s + 16];
            float4 b0 = w2p[s], b1 = w2p[s + 16];
            const int nlm = 2 * l + 1;
            #pragma unroll
            for (int j = 0; j < nlm; j++) {
                const float4* rp = sfp + (l * l + j) * 32;
                float4 v0 = rp[s], v1 = rp[s + 16];
                s1[r] = dot4(v0, a0) + dot4(v1, a1);
                s2[r] = dot4(v0, b0) + dot4(v1, b1);
                r++;
            }
        }
    }

    // ---- phase 2: width-16 butterfly (stays inside the half-warp) ----
    #pragma unroll
    for (int r = 0; r < 9; r++) {
        #pragma unroll
        for (int d = 1; d < 16; d <<= 1) {
            s1[r] += __shfl_xor_sync(0xffffffffu, s1[r], d);
            s2[r] += __shfl_xor_sync(0xffffffffu, s2[r], d);
        }
    }
    if (h == 0) { s1[0] += c1; s2[0] += c2; }   // bias on even-parity scalar channel

    if (s == 0) {
        #pragma unroll
        for (int r = 0; r < 9; r++) {
            xbuf[warp][h * 9 + r]      = s1[r];
            xbuf[warp][18 + h * 9 + r] = s2[r];
        }
    }
    __syncwarp();

    // ---- phase 3: sparse tensor product tp[c] (lanes 0-8) ----
    if (lane < 9) {
        int c = lane;
        float tp = 0.f;
        int cnt = lcnt_s[c];
        const unsigned char* pab = lab_s + c * MAXE;
        const float*         pv  = lval_s + c * MAXE;
        for (int e = 0; e < cnt; e++) {
            int ab = pab[e];
            float val = pv[e];
            int a = ab >> 4, b = ab & 15;
            float t0 = xbuf[warp][a] * xbuf[warp][18 + b];
            float t1 = fmaf(xbuf[warp][9 + a], xbuf[warp][27 + b], t0);
            tp = fmaf(val, t1, tp);
        }
        tpbuf[warp][c] = tp;
    }
    __syncwarp();

    // ---- phase 4: out[i,j] = sum_c tp[c] * CG[1+i,1+j,c] (lanes 0-8) ----
    if (lane < 9 && active) {
        int k = lane;
        float o = 0.f;
        #pragma unroll
        for (int c = 0; c < 9; c++) o = fmaf(tpbuf[warp][c], cgos[k * 9 + c], o);
        out[(size_t)n * 9 + k] = o;
    }
}

// ================= launch =================
extern "C" void kernel_launch(void* const* d_in, const int* in_sizes, int n_in,
                              void* d_out, int out_size) {
    const float* sf    = (const float*)d_in[0];
    const float* W3    = (const float*)d_in[1];
    const float* b3    = (const float*)d_in[2];
    const float* Wt1   = (const float*)d_in[3];
    const float* bt1   = (const float*)d_in[4];
    const float* Wt2   = (const float*)d_in[5];
    const float* bt2   = (const float*)d_in[6];
    const float* wpath = (const float*)d_in[7];

    int N = in_sizes[0] / 2304;  // N * 2 * 9 * 128

    // ---- host-side constant construction (pure CPU, graph-safe) ----
    float cg[729];
    h_build_cg(cg);

    PrepConst pc;
    MainConst mcst;
    memset(&pc, 0, sizeof(pc));
    memset(&mcst, 0, sizeof(mcst));

    for (int t = 0; t < 81; t++) {
        int k = t / 9, c = t % 9;
        int ii = k / 3, jj = k % 3;
        mcst.cgos[t] = cg[(1 + ii) * 81 + (1 + jj) * 9 + c];
    }
    for (int c = 0; c < 9; c++) {
        int cnt = 0;
        for (int ab = 0; ab < 81; ab++) {
            int idx = ab * 9 + c;
            if (fabsf(cg[idx]) > 1e-6f && cnt < MAXE) {
                int a = ab / 9, b = ab % 9;
                mcst.lab[c * MAXE + cnt] = (unsigned char)((a << 4) | b);
                pc.cgv[c * MAXE + cnt]   = cg[idx];
                pc.wpidx[c * MAXE + cnt] = (unsigned char)((h_lof(a) * 3 + h_lof(b)) * 3 + h_lof(c));
                cnt++;
            }
        }
        mcst.lcnt[c] = cnt;
    }

    // ---- device work: parallel prelude + streaming kernel ----
    k_prep<<<97, 256>>>(W3, b3, Wt1, bt1, Wt2, bt2, wpath, pc);

    int blocks = (N + 7) / 8;                    // 8 n per block (1 n per warp)
    k_main<<<blocks, 256>>>(sf, (float*)d_out, N, mcst);
}

// round 14
// speedup vs baseline: 1.1625x; 1.1285x over previous
#include <cuda_runtime.h>
#include <math.h>
#include <string.h>

#define MAXE 48

// ---------------- device-global scratch (weight/wpath-dependent only) ----------------
__device__ float g_w1[768];          // pre-contracted W3@Wt1 : [p][l][128]
__device__ float g_w2[768];          // pre-contracted W3@Wt2
__device__ float g_c1, g_c2;         // bias scalars for (p=0, lm=0)
__device__ float g_lval[9 * MAXE];   // CG * wpath, per-c sparse lists

// ---------------- host-computed constants passed by value (constant bank) ----------------
struct PrepConst {
    float         cgv[9 * MAXE];     // CG value per sparse entry (0 in unused slots)
    unsigned char wpidx[9 * MAXE];   // wpath flat index per sparse entry
};
struct MainConst {
    float         cgos[81];          // CG[1+i][1+j][c] laid out [k=i*3+j][c]
    int           lcnt[9];           // sparse-list counts per output c
    unsigned char lab[9 * MAXE];     // packed (a<<4)|b per sparse entry
};

// ================= HOST: Clebsch-Gordan construction (double precision) =================
static inline int h_lof(int i) { return i >= 4 ? 2 : (i >= 1 ? 1 : 0); }

static double h_dfact(int n) {
    static const double F[8] = {1., 1., 2., 6., 24., 120., 720., 5040.};
    return F[n];
}

static double h_cg_complex(int j1, int m1, int j2, int m2, int j3, int m3) {
    if (m3 != m1 + m2) return 0.0;
    int lo = j1 - j2; if (lo < 0) lo = -lo;
    if (j3 < lo || j3 > j1 + j2) return 0.0;
    double pref = sqrt((2.0 * j3 + 1.0) * h_dfact(j1 + j2 - j3) * h_dfact(j1 - j2 + j3) *
                       h_dfact(-j1 + j2 + j3) / h_dfact(j1 + j2 + j3 + 1));
    pref *= sqrt(h_dfact(j1 + m1) * h_dfact(j1 - m1) * h_dfact(j2 + m2) * h_dfact(j2 - m2) *
                 h_dfact(j3 + m3) * h_dfact(j3 - m3));
    double s = 0.0;
    for (int k = 0; k <= j1 + j2 - j3; k++) {
        int t1 = j1 + j2 - j3 - k, t2 = j1 - m1 - k, t3 = j2 + m2 - k;
        int t4 = j3 - j2 + m1 + k, t5 = j3 - j1 - m2 + k;
        if (t1 < 0 || t2 < 0 || t3 < 0 || t4 < 0 || t5 < 0) continue;
        double d = h_dfact(k) * h_dfact(t1) * h_dfact(t2) * h_dfact(t3) * h_dfact(t4) * h_dfact(t5);
        s += ((k & 1) ? -1.0 : 1.0) / d;
    }
    return pref * s;
}

// complex->real basis matrix entry; rows ordered m=-l..l. r,c in 0..2l
static void h_umat_entry(int l, int r, int c, double* re, double* im) {
    *re = 0.0; *im = 0.0;
    int mr = r - l, mc = c - l;
    const double inv = 0.70710678118654752440;
    if (mr == 0) { if (mc == 0) *re = 1.0; return; }
    if (mr > 0) {
        int m = mr; double sgn = (m & 1) ? -1.0 : 1.0;
        if (mc == -m) *re = inv;
        else if (mc == m) *re = sgn * inv;
    } else {
        int m = -mr; double sgn = (m & 1) ? -1.0 : 1.0;
        if (mc == -m) *im = inv;
        else if (mc == m) *im = -sgn * inv;
    }
}

static void h_build_cg(float* cg /*729*/) {
    for (int t = 0; t < 729; t++) {
        int a = t / 81, b = (t / 9) % 9, c = t % 9;
        int l1 = h_lof(a), l2 = h_lof(b), l3 = h_lof(c);
        double re = 0.0, im = 0.0;
        int lo = l1 - l2; if (lo < 0) lo = -lo;
        if (l3 >= lo && l3 <= l1 + l2) {
            int aa = a - l1 * l1, bb = b - l2 * l2, cc = c - l3 * l3;
            for (int m = 0; m < 2 * l1 + 1; m++) {
                double u1r, u1i; h_umat_entry(l1, aa, m, &u1r, &u1i); u1i = -u1i;  // conj
                if (u1r == 0.0 && u1i == 0.0) continue;
                for (int nn = 0; nn < 2 * l2 + 1; nn++) {
                    double u2r, u2i; h_umat_entry(l2, bb, nn, &u2r, &u2i); u2i = -u2i;  // conj
                    if (u2r == 0.0 && u2i == 0.0) continue;
                    double pr = u1r * u2r - u1i * u2i;
                    double pi = u1r * u2i + u1i * u2r;
                    for (int o = 0; o < 2 * l3 + 1; o++) {
                        double u3r, u3i; h_umat_entry(l3, cc, o, &u3r, &u3i);
                        if (u3r == 0.0 && u3i == 0.0) continue;
                        double C = h_cg_complex(l1, m - l1, l2, nn - l2, l3, o - l3);
                        if (C == 0.0) continue;
                        re += (pr * u3r - pi * u3i) * C;
                        im += (pr * u3i + pi * u3r) * C;
                    }
                }
            }
        }
        double val = ((l1 + l2 + l3) & 1) ? im : re;
        cg[t] = (float)val;
    }
}

// ================= DEVICE: prelude — warp-per-output dot products (measured ~1.5us) ======
__device__ __forceinline__ float dot4(float4 v, float4 w) {
    return fmaf(v.x, w.x, fmaf(v.y, w.y, fmaf(v.z, w.z, v.w * w.w)));
}

// grid = 97 blocks of 256. Blocks 0..95: 8 warps each, warp computes one of 768
// pre-contracted weights (128-dot spread over 32 lanes). Block 96: warp 0 does the
// bias dot; warps 1..7 scale the sparse CG lists by wpath.
__global__ void k_prep(const float* __restrict__ W3, const float* __restrict__ b3,
                       const float* __restrict__ Wt1, const float* __restrict__ bt1,
                       const float* __restrict__ Wt2, const float* __restrict__ bt2,
                       const float* __restrict__ wpath, PrepConst pc) {
    int tid = threadIdx.x;
    int warp = tid >> 5, lane = tid & 31;

    if (blockIdx.x < 96) {
        int t = blockIdx.x * 8 + warp;            // 0..767 output index
        int pl = t >> 7;
        const float4* w3r = reinterpret_cast<const float4*>(W3) + (size_t)t * 32;
        const float4* v1r = reinterpret_cast<const float4*>(Wt1) + pl * 32;
        const float4* v2r = reinterpret_cast<const float4*>(Wt2) + pl * 32;
        float4 w = w3r[lane];
        float a1 = dot4(w, v1r[lane]);
        float a2 = dot4(w, v2r[lane]);
        #pragma unroll
        for (int d = 16; d > 0; d >>= 1) {
            a1 += __shfl_xor_sync(0xffffffffu, a1, d);
            a2 += __shfl_xor_sync(0xffffffffu, a2, d);
        }
        if (lane == 0) { g_w1[t] = a1; g_w2[t] = a2; }
    } else {
        if (warp == 0) {
            const float4* br  = reinterpret_cast<const float4*>(b3);
            const float4* v1r = reinterpret_cast<const float4*>(Wt1);
            const float4* v2r = reinterpret_cast<const float4*>(Wt2);
            float4 b = br[lane];
            float a1 = dot4(b, v1r[lane]);
            float a2 = dot4(b, v2r[lane]);
            #pragma unroll
            for (int d = 16; d > 0; d >>= 1) {
                a1 += __shfl_xor_sync(0xffffffffu, a1, d);
                a2 += __shfl_xor_sync(0xffffffffu, a2, d);
            }
            if (lane == 0) { g_c1 = a1 + bt1[0]; g_c2 = a2 + bt2[0]; }
        } else {
            for (int i = tid - 32; i < 9 * MAXE; i += 224)
                g_lval[i] = pc.cgv[i] * wpath[pc.wpidx[i]];
        }
    }
}

// ================= DEVICE: main streaming kernel (R12 structure: 108us @ 71% DRAM) ======
// 4 n per warp, 8-lane subgroups. Lane owns float4 stripes {s, s+8, s+16, s+24} of
// each 512B row -> 72 dependency-free LDG.128 per warp (per-warp MLP at the M_max cap),
// each LDG covering 4 full 128B lines.
__global__ void __launch_bounds__(256, 2)
k_main(const float* __restrict__ sf, float* __restrict__ out, int N, MainConst mc) {
    __shared__ float w1s[768];
    __shared__ float w2s[768];
    __shared__ float cgos[81];
    __shared__ int   lcnt_s[9];
    __shared__ unsigned char lab_s[9 * MAXE];
    __shared__ float lval_s[9 * MAXE];
    __shared__ float xbuf[32][36];       // per-subgroup x1[18], x2[18]
    __shared__ float tpbuf[32][9];

    int tid = threadIdx.x;
    for (int i = tid; i < 768; i += 256) { w1s[i] = g_w1[i]; w2s[i] = g_w2[i]; }
    for (int i = tid; i < 9 * MAXE; i += 256) { lval_s[i] = g_lval[i]; lab_s[i] = mc.lab[i]; }
    if (tid < 81) cgos[tid] = mc.cgos[tid];
    if (tid < 9)  lcnt_s[tid] = mc.lcnt[tid];
    float c1 = g_c1, c2 = g_c2;
    __syncthreads();

    int warp = tid >> 5, lane = tid & 31;
    int g = lane >> 3, s = lane & 7;            // 4 subgroups of 8 lanes; one n per subgroup
    int sub = (warp << 2) | g;
    int n = (blockIdx.x * 8 + warp) * 4 + g;
    bool active = n < N;
    size_t nn = active ? (size_t)n : 0;

    const float4* sfp = reinterpret_cast<const float4*>(sf) + nn * 576;  // 2*9*32 float4 per n

    // ---- phase 1: 36 partial dots, all 72 LDG.128 dependency-free (max MLP) ----
    float s1[18], s2[18];
    {
        int r = 0;
        #pragma unroll
        for (int p = 0; p < 2; p++) {
            #pragma unroll
            for (int l = 0; l < 3; l++) {
                const float4* w1p = reinterpret_cast<const float4*>(w1s) + (p * 3 + l) * 32;
                const float4* w2p = reinterpret_cast<const float4*>(w2s) + (p * 3 + l) * 32;
                float4 a0 = w1p[s], a1 = w1p[s + 8], a2 = w1p[s + 16], a3 = w1p[s + 24];
                float4 b0 = w2p[s], b1 = w2p[s + 8], b2 = w2p[s + 16], b3v = w2p[s + 24];
                const int nlm = 2 * l + 1;
                #pragma unroll
                for (int j = 0; j < nlm; j++) {
                    const float4* rp = sfp + (p * 9 + l * l + j) * 32;
                    float4 v0 = rp[s], v1 = rp[s + 8], v2 = rp[s + 16], v3 = rp[s + 24];
                    s1[r] = dot4(v0, a0) + dot4(v1, a1) + dot4(v2, a2) + dot4(v3, a3);
                    s2[r] = dot4(v0, b0) + dot4(v1, b1) + dot4(v2, b2) + dot4(v3, b3v);
                    r++;
                }
            }
        }
    }

    // ---- phase 2: width-8 butterfly reduction (stays inside subgroup) ----
    #pragma unroll
    for (int r = 0; r < 18; r++) {
        s1[r] += __shfl_xor_sync(0xffffffffu, s1[r], 1);
        s1[r] += __shfl_xor_sync(0xffffffffu, s1[r], 2);
        s1[r] += __shfl_xor_sync(0xffffffffu, s1[r], 4);
        s2[r] += __shfl_xor_sync(0xffffffffu, s2[r], 1);
        s2[r] += __shfl_xor_sync(0xffffffffu, s2[r], 2);
        s2[r] += __shfl_xor_sync(0xffffffffu, s2[r], 4);
    }
    s1[0] += c1;   // bias on even-parity scalar channel
    s2[0] += c2;

    if (s == 0) {
        #pragma unroll
        for (int r = 0; r < 18; r++) { xbuf[sub][r] = s1[r]; xbuf[sub][18 + r] = s2[r]; }
    }
    __syncwarp();

    // ---- phase 3: sparse tensor product tp[c] (lanes split the 9 c's) ----
    for (int c = s; c < 9; c += 8) {
        float tp = 0.f;
        int cnt = lcnt_s[c];
        const unsigned char* pab = lab_s + c * MAXE;
        const float*         pv  = lval_s + c * MAXE;
        for (int e = 0; e < cnt; e++) {
            int ab = pab[e];
            float val = pv[e];
            int a = ab >> 4, b = ab & 15;
            float t0 = xbuf[sub][a] * xbuf[sub][18 + b];
            float t1 = fmaf(xbuf[sub][9 + a], xbuf[sub][27 + b], t0);
            tp = fmaf(val, t1, tp);
        }
        tpbuf[sub][c] = tp;
    }
    __syncwarp();

    // ---- phase 4: out[i,j] = sum_c tp[c] * CG[1+i,1+j,c] ----
    for (int k = s; k < 9; k += 8) {
        float o = 0.f;
        #pragma unroll
        for (int c = 0; c < 9; c++) o = fmaf(tpbuf[sub][c], cgos[k * 9 + c], o);
        if (active) out[(size_t)n * 9 + k] = o;
    }
}

// ================= launch =================
extern "C" void kernel_launch(void* const* d_in, const int* in_sizes, int n_in,
                              void* d_out, int out_size) {
    const float* sf    = (const float*)d_in[0];
    const float* W3    = (const float*)d_in[1];
    const float* b3    = (const float*)d_in[2];
    const float* Wt1   = (const float*)d_in[3];
    const float* bt1   = (const float*)d_in[4];
    const float* Wt2   = (const float*)d_in[5];
    const float* bt2   = (const float*)d_in[6];
    const float* wpath = (const float*)d_in[7];

    int N = in_sizes[0] / 2304;  // N * 2 * 9 * 128

    // ---- host-side constant construction (pure CPU, graph-safe) ----
    float cg[729];
    h_build_cg(cg);

    PrepConst pc;
    MainConst mcst;
    memset(&pc, 0, sizeof(pc));
    memset(&mcst, 0, sizeof(mcst));

    for (int t = 0; t < 81; t++) {
        int k = t / 9, c = t % 9;
        int ii = k / 3, jj = k % 3;
        mcst.cgos[t] = cg[(1 + ii) * 81 + (1 + jj) * 9 + c];
    }
    for (int c = 0; c < 9; c++) {
        int cnt = 0;
        for (int ab = 0; ab < 81; ab++) {
            int idx = ab * 9 + c;
            if (fabsf(cg[idx]) > 1e-6f && cnt < MAXE) {
                int a = ab / 9, b = ab % 9;
                mcst.lab[c * MAXE + cnt] = (unsigned char)((a << 4) | b);
                pc.cgv[c * MAXE + cnt]   = cg[idx];
                pc.wpidx[c * MAXE + cnt] = (unsigned char)((h_lof(a) * 3 + h_lof(b)) * 3 + h_lof(c));
                cnt++;
            }
        }
        mcst.lcnt[c] = cnt;
    }

    // ---- device work: parallel prelude + streaming kernel ----
    k_prep<<<97, 256>>>(W3, b3, Wt1, bt1, Wt2, bt2, wpath, pc);

    int blocks = (N + 31) / 32;                  // 32 n per block (8 warps x 4 subgroups)
    k_main<<<blocks, 256>>>(sf, (float*)d_out, N, mcst);
}